// round 15
// baseline (speedup 1.0000x reference)
#include <cuda_runtime.h>
#include <cuda_bf16.h>

// Problem constants
#define BATCH   16
#define HDIM    224
#define WDIM    224
#define CDIM    64
#define HO      112
#define WO      112
#define NPATCH  (HO * WO)            // 12544 per image
#define TOPK    1254

// float4-unit strides for x [B,H,W,C] NHWC
#define IMG4    (HDIM * WDIM * (CDIM / 4))   // 802816
#define ROW4    (WDIM * (CDIM / 4))          // 3584
#define PIX4    (CDIM / 4)                   // 16
#define QTR4    (IMG4 / 4)                   // 200704 (56 rows)

#define NBINS   4096                 // top-12-bit histogram
#define MAXCAND 2048
#define CBLKS   392                  // conv blocks per image

// Scratch (no cudaMalloc allowed). Device globals are zero-initialized at
// module load; the tail selector re-zeroes d_hist / d_arrive at its end, so
// every kernel_launch invocation starts clean (deterministic).
__device__ float    d_g[BATCH * NPATCH];
__device__ unsigned d_hist[BATCH * NBINS];
__device__ unsigned d_thr[BATCH];
__device__ unsigned d_arrive[BATCH];

// Order-preserving float->uint transform (ascending uint == ascending float)
__device__ __forceinline__ unsigned f2o(float f) {
    unsigned u = __float_as_uint(f);
    return (u & 0x80000000u) ? ~u : (u | 0x80000000u);
}

// Shared scratch for the tail selector (~14.5 KB; conv itself uses no smem)
struct SelShared {
    unsigned       cand_u[MAXCAND];
    unsigned short cand_i[MAXCAND];
    unsigned       partial[256];
    unsigned       wsum[8];
    unsigned       h2[256];
    unsigned       pref, rem, cnt, claim;
    int            is_last;
};

// ---------------------------------------------------------------------------
// Kernel 1: gating conv (2x2, stride 2, 1 out-channel), 4 patches per warp,
// fused top-12-bit histogram, PLUS tail-block per-image top-K threshold
// selection. Fences are tid0-ONLY (gpu-scope fence emits CCTL.IVALL = L1D
// invalidate; doing it per-thread in R11 cost ~9us). Block-scope ordering of
// all threads' d_g stores comes from __syncthreads(); tid0's release fence +
// arrival atomic then makes them gpu-visible (cumulativity), and the
// selector's tid0 acquire fence + __syncthreads() publishes them block-wide.
// ---------------------------------------------------------------------------
__global__ void __launch_bounds__(256) conv_gate_k(
        const float* __restrict__ x, const float* __restrict__ wk) {
    __shared__ SelShared S;

    int b    = blockIdx.y;
    int warp = threadIdx.x >> 5;
    int lane = threadIdx.x & 31;
    int tid  = threadIdx.x;
    int q    = blockIdx.x * 8 + warp;      // quad index in [0, 3136)
    int ho   = q / 28;
    int wq   = q - ho * 28;

    const float4* x4 = (const float4*)x;
    const float4* w4 = (const float4*)wk;

    int r0 = b * IMG4 + (2 * ho) * ROW4 + (8 * wq) * PIX4;
    int r1 = r0 + ROW4;

    float4 wa = __ldg(&w4[lane]);
    float4 wb = __ldg(&w4[lane + 32]);

    float s[4];
    #pragma unroll
    for (int k = 0; k < 4; k++) {
        float4 a = __ldg(&x4[r0 + 32 * k + lane]);
        float4 c = __ldg(&x4[r1 + 32 * k + lane]);
        s[k] = a.x * wa.x + a.y * wa.y + a.z * wa.z + a.w * wa.w
             + c.x * wb.x + c.y * wb.y + c.z * wb.z + c.w * wb.w;
    }
    #pragma unroll
    for (int o = 16; o; o >>= 1) {
        #pragma unroll
        for (int k = 0; k < 4; k++)
            s[k] += __shfl_xor_sync(0xffffffffu, s[k], o);
    }
    if (lane < 4)
        atomicAdd(&d_hist[b * NBINS + (f2o(s[lane]) >> 20)], 1u);
    if (lane == 0) {
        float4* g4 = (float4*)d_g;
        g4[(b * NPATCH) / 4 + ho * 28 + wq] = make_float4(s[0], s[1], s[2], s[3]);
    }

    // ---- arrival: last block of this image becomes the selector ----
    __syncthreads();                       // orders ALL threads' d_g stores
    if (tid == 0) {
        __threadfence();                   // tid0-only release (one CCTL/block)
        S.is_last = (atomicAdd(&d_arrive[b], 1u) == CBLKS - 1);
    }
    __syncthreads();
    if (!S.is_last) return;
    if (tid == 0) __threadfence();         // tid0-only acquire
    __syncthreads();

    const float* g = d_g + b * NPATCH;
    const unsigned* hist = d_hist + b * NBINS;

    // a) scan 4096-bin hist (16 bins/thread) from the top -> pref12 + rem
    unsigned psum = 0;
    #pragma unroll
    for (int k = 0; k < 16; k++) psum += hist[tid * 16 + k];
    S.partial[tid] = psum;
    unsigned ws = psum;
    #pragma unroll
    for (int o = 16; o; o >>= 1) ws += __shfl_xor_sync(0xffffffffu, ws, o);
    if (lane == 0) S.wsum[warp] = ws;
    __syncthreads();

    if (tid == 0) {
        int rem = TOPK;
        int w = 7;
        for (; w > 0; --w) { if (rem > (int)S.wsum[w]) rem -= (int)S.wsum[w]; else break; }
        int t = w * 32 + 31;
        for (; t > w * 32; --t) { if (rem > (int)S.partial[t]) rem -= (int)S.partial[t]; else break; }
        int d = t * 16 + 15;
        for (; d > t * 16; --d) { if (rem > (int)hist[d]) rem -= (int)hist[d]; else break; }
        S.pref = (unsigned)d;              // 12-bit prefix
        S.rem  = (unsigned)rem;
        S.cnt  = 0;
        S.claim = 0;
    }
    __syncthreads();

    // b) gather candidates whose top-12 bits match (d_g is L2-resident)
    unsigned pref12 = S.pref;
    for (int i = tid; i < NPATCH; i += 256) {
        unsigned u = f2o(g[i]);
        if ((u >> 20) == pref12) {
            unsigned pos = atomicAdd(&S.cnt, 1u);
            if (pos < MAXCAND) { S.cand_u[pos] = u; S.cand_i[pos] = (unsigned short)i; }
        }
    }
    __syncthreads();
    int cnt = min(S.cnt, (unsigned)MAXCAND);

    // c) byte-wise refine of the low 20 bits: bits [19:12], [11:4], [3:0]
    S.h2[tid] = 0; __syncthreads();
    for (int i = tid; i < cnt; i += 256)
        atomicAdd(&S.h2[(S.cand_u[i] >> 12) & 255u], 1u);
    __syncthreads();
    if (tid == 0) {
        int rem = (int)S.rem; int d = 255;
        for (; d > 0; --d) { if (rem > (int)S.h2[d]) rem -= (int)S.h2[d]; else break; }
        S.pref = (S.pref << 8) | (unsigned)d;   // 20-bit prefix
        S.rem = (unsigned)rem;
    }
    __syncthreads();
    unsigned pref20 = S.pref;
    S.h2[tid] = 0; __syncthreads();
    for (int i = tid; i < cnt; i += 256) {
        unsigned u = S.cand_u[i];
        if ((u >> 12) == pref20) atomicAdd(&S.h2[(u >> 4) & 255u], 1u);
    }
    __syncthreads();
    if (tid == 0) {
        int rem = (int)S.rem; int d = 255;
        for (; d > 0; --d) { if (rem > (int)S.h2[d]) rem -= (int)S.h2[d]; else break; }
        S.pref = (S.pref << 8) | (unsigned)d;   // 28-bit prefix
        S.rem = (unsigned)rem;
    }
    __syncthreads();
    unsigned pref28 = S.pref;
    if (tid < 16) S.h2[tid] = 0;
    __syncthreads();
    for (int i = tid; i < cnt; i += 256) {
        unsigned u = S.cand_u[i];
        if ((u >> 4) == pref28) atomicAdd(&S.h2[u & 15u], 1u);
    }
    __syncthreads();
    if (tid == 0) {
        int rem = (int)S.rem; int d = 15;
        for (; d > 0; --d) { if (rem > (int)S.h2[d]) rem -= (int)S.h2[d]; else break; }
        S.pref = (S.pref << 4) | (unsigned)d;   // full 32-bit threshold
        S.rem = (unsigned)rem;
    }
    __syncthreads();

    // d) tie cleanup: keep exactly S.rem threshold-valued elements
    unsigned thr = S.pref, keep = S.rem;
    for (int i = tid; i < cnt; i += 256) {
        if (S.cand_u[i] == thr) {
            unsigned pcl = atomicAdd(&S.claim, 1u);
            if (pcl >= keep)
                d_g[b * NPATCH + S.cand_i[i]] = __uint_as_float(0xFF800000u); // -inf
        }
    }
    if (tid == 0) d_thr[b] = thr;

    // e) reset this image's histogram + arrival counter for the next call
    __syncthreads();
    #pragma unroll
    for (int k = 0; k < 16; k++)
        d_hist[b * NBINS + k * 256 + tid] = 0u;
    if (tid == 0) d_arrive[b] = 0u;
}

// ---------------------------------------------------------------------------
// Kernel 2: out = x * gate, ILP-4 (best-measured shape: 36.1us, occ 75%).
// Gate computed inline from the RAW score via threshold compare. 32
// consecutive float4 = one gate cell -> warp-uniform; zero cells skip the x
// read. Streaming stores (evict-first) for the never-re-read output.
// ---------------------------------------------------------------------------
__global__ void __launch_bounds__(256) apply_gate_k(
        const float* __restrict__ x, float* __restrict__ out) {
    int b     = blockIdx.y;
    int h     = blockIdx.x / 14;                            // 0..55
    int w4off = (blockIdx.x - h * 14) * 256 + threadIdx.x;  // 0..3583
    int w     = w4off >> 4;

    unsigned thr = __ldg(&d_thr[b]);
    const float* gb = d_g + b * NPATCH;
    int gcol = w >> 1;
    int grow = h >> 1;

    float gv[4];
    #pragma unroll
    for (int j = 0; j < 4; j++) {
        float s = __ldg(&gb[(grow + 28 * j) * WO + gcol]);
        gv[j] = (f2o(s) >= thr) ? s : 0.0f;
    }

    int i0 = b * IMG4 + h * ROW4 + w4off;
    const float4* x4 = (const float4*)x;
    float4*       o4 = (float4*)out;

    float4 r[4];
    #pragma unroll
    for (int j = 0; j < 4; j++) {
        float gg = gv[j];
        if (gg != 0.0f) {
            float4 v = __ldg(&x4[i0 + j * QTR4]);
            r[j] = make_float4(v.x * gg, v.y * gg, v.z * gg, v.w * gg);
        } else {
            r[j] = make_float4(0.f, 0.f, 0.f, 0.f);
        }
    }
    #pragma unroll
    for (int j = 0; j < 4; j++)
        __stcs(&o4[i0 + j * QTR4], r[j]);
}

// ---------------------------------------------------------------------------
extern "C" void kernel_launch(void* const* d_in, const int* in_sizes, int n_in,
                              void* d_out, int out_size) {
    const float* x  = (const float*)d_in[0];
    const float* wk = (const float*)d_in[1];
    float* out = (float*)d_out;

    // 1) conv + fused histogram + tail-block per-image threshold select
    dim3 cgrid(CBLKS, BATCH);
    conv_gate_k<<<cgrid, 256>>>(x, wk);

    // 2) apply gate, ILP-4, streaming stores
    dim3 agrid(14 * 56, BATCH);
    apply_gate_k<<<agrid, 256>>>(x, out);
}

// round 17
// speedup vs baseline: 1.0239x; 1.0239x over previous
#include <cuda_runtime.h>
#include <cuda_bf16.h>

// Problem constants
#define BATCH   16
#define HDIM    224
#define WDIM    224
#define CDIM    64
#define HO      112
#define WO      112
#define NPATCH  (HO * WO)            // 12544 per image
#define TOPK    1254

// float4-unit strides for x [B,H,W,C] NHWC
#define IMG4    (HDIM * WDIM * (CDIM / 4))   // 802816
#define ROW4    (WDIM * (CDIM / 4))          // 3584
#define PIX4    (CDIM / 4)                   // 16
#define QTR4    (IMG4 / 4)                   // 200704 (56 rows)

#define NBINS   4096                 // top-12-bit histogram
#define MAXCAND 2048
#define APB     784                  // apply blocks per image (14*56)

// Scratch (no cudaMalloc allowed). Device globals are zero-initialized at
// module load; the selector/resetter blocks restore d_hist, d_thr, d_adone
// to zero at the end of every invocation (deterministic).
__device__ float    d_g[BATCH * NPATCH];
__device__ unsigned d_hist[BATCH * NBINS];
__device__ unsigned d_thr[BATCH];     // 0 = "not ready" sentinel
__device__ unsigned d_adone[BATCH];

// Order-preserving float->uint transform (ascending uint == ascending float)
__device__ __forceinline__ unsigned f2o(float f) {
    unsigned u = __float_as_uint(f);
    return (u & 0x80000000u) ? ~u : (u | 0x80000000u);
}

// Shared scratch (selector path; apply path reuses only .pref)
struct SelShared {
    unsigned       cand_u[MAXCAND];
    unsigned short cand_i[MAXCAND];
    unsigned       partial[256];
    unsigned       wsum[8];
    unsigned       h2[256];
    unsigned       pref, rem, cnt, claim;
};

// ---------------------------------------------------------------------------
// Kernel 1: gating conv (2x2, stride 2, 1 out-channel), 4 patches per warp,
// fused top-12-bit histogram accumulation. (Unchanged R14-best: 35.5us.)
// ---------------------------------------------------------------------------
__global__ void __launch_bounds__(256) conv_gate_k(
        const float* __restrict__ x, const float* __restrict__ wk) {
    int b    = blockIdx.y;
    int warp = threadIdx.x >> 5;
    int lane = threadIdx.x & 31;
    int q    = blockIdx.x * 8 + warp;      // quad index in [0, 3136)
    int ho   = q / 28;
    int wq   = q - ho * 28;

    const float4* x4 = (const float4*)x;
    const float4* w4 = (const float4*)wk;

    int r0 = b * IMG4 + (2 * ho) * ROW4 + (8 * wq) * PIX4;
    int r1 = r0 + ROW4;

    float4 wa = __ldg(&w4[lane]);
    float4 wb = __ldg(&w4[lane + 32]);

    float s[4];
    #pragma unroll
    for (int k = 0; k < 4; k++) {
        float4 a = __ldg(&x4[r0 + 32 * k + lane]);
        float4 c = __ldg(&x4[r1 + 32 * k + lane]);
        s[k] = a.x * wa.x + a.y * wa.y + a.z * wa.z + a.w * wa.w
             + c.x * wb.x + c.y * wb.y + c.z * wb.z + c.w * wb.w;
    }
    #pragma unroll
    for (int o = 16; o; o >>= 1) {
        #pragma unroll
        for (int k = 0; k < 4; k++)
            s[k] += __shfl_xor_sync(0xffffffffu, s[k], o);
    }
    if (lane < 4)
        atomicAdd(&d_hist[b * NBINS + (f2o(s[lane]) >> 20)], 1u);
    if (lane == 0) {
        float4* g4 = (float4*)d_g;
        g4[(b * NPATCH) / 4 + ho * 28 + wq] = make_float4(s[0], s[1], s[2], s[3]);
    }
}

// ---------------------------------------------------------------------------
// Kernel 2: fused select + apply.
//   blocks 0..15  : per-image threshold selector (hist scan + candidate
//                   gather + byte-wise refine + tie cleanup), then RELEASE
//                   the threshold via d_thr[b] (sentinel 0 -> thr != 0).
//                   Guaranteed wave-1 resident (lowest 16 bids) -> no deadlock.
//   blocks 16..   : apply blocks; tid0 spins on d_thr[b] (nanosleep), then
//                   the block gates 4 image-quarter float4 cells (ILP-4,
//                   warp-uniform gate, streaming stores). Last apply block
//                   per image resets d_thr/d_adone for the next invocation.
// ---------------------------------------------------------------------------
__global__ void __launch_bounds__(256) selapply_k(
        const float* __restrict__ x, float* __restrict__ out) {
    __shared__ SelShared S;
    int tid = threadIdx.x;

    if (blockIdx.x < BATCH) {
        // ================= selector path =================
        int b = blockIdx.x;
        int lane = tid & 31, warp = tid >> 5;
        const float* g = d_g + b * NPATCH;
        const unsigned* hist = d_hist + b * NBINS;

        // a) scan 4096-bin hist (16 bins/thread) from the top -> pref12 + rem
        unsigned psum = 0;
        #pragma unroll
        for (int k = 0; k < 16; k++) psum += hist[tid * 16 + k];
        S.partial[tid] = psum;
        unsigned ws = psum;
        #pragma unroll
        for (int o = 16; o; o >>= 1) ws += __shfl_xor_sync(0xffffffffu, ws, o);
        if (lane == 0) S.wsum[warp] = ws;
        __syncthreads();

        if (tid == 0) {
            int rem = TOPK;
            int w = 7;
            for (; w > 0; --w) { if (rem > (int)S.wsum[w]) rem -= (int)S.wsum[w]; else break; }
            int t = w * 32 + 31;
            for (; t > w * 32; --t) { if (rem > (int)S.partial[t]) rem -= (int)S.partial[t]; else break; }
            int d = t * 16 + 15;
            for (; d > t * 16; --d) { if (rem > (int)hist[d]) rem -= (int)hist[d]; else break; }
            S.pref = (unsigned)d;          // 12-bit prefix
            S.rem  = (unsigned)rem;
            S.cnt  = 0;
            S.claim = 0;
        }
        __syncthreads();

        // b) gather candidates whose top-12 bits match (d_g is L2-resident)
        unsigned pref12 = S.pref;
        for (int i = tid; i < NPATCH; i += 256) {
            unsigned u = f2o(g[i]);
            if ((u >> 20) == pref12) {
                unsigned pos = atomicAdd(&S.cnt, 1u);
                if (pos < MAXCAND) { S.cand_u[pos] = u; S.cand_i[pos] = (unsigned short)i; }
            }
        }
        __syncthreads();
        int cnt = min(S.cnt, (unsigned)MAXCAND);

        // c) byte-wise refine of low 20 bits: [19:12], [11:4], [3:0]
        S.h2[tid] = 0; __syncthreads();
        for (int i = tid; i < cnt; i += 256)
            atomicAdd(&S.h2[(S.cand_u[i] >> 12) & 255u], 1u);
        __syncthreads();
        if (tid == 0) {
            int rem = (int)S.rem; int d = 255;
            for (; d > 0; --d) { if (rem > (int)S.h2[d]) rem -= (int)S.h2[d]; else break; }
            S.pref = (S.pref << 8) | (unsigned)d;
            S.rem = (unsigned)rem;
        }
        __syncthreads();
        unsigned pref20 = S.pref;
        S.h2[tid] = 0; __syncthreads();
        for (int i = tid; i < cnt; i += 256) {
            unsigned u = S.cand_u[i];
            if ((u >> 12) == pref20) atomicAdd(&S.h2[(u >> 4) & 255u], 1u);
        }
        __syncthreads();
        if (tid == 0) {
            int rem = (int)S.rem; int d = 255;
            for (; d > 0; --d) { if (rem > (int)S.h2[d]) rem -= (int)S.h2[d]; else break; }
            S.pref = (S.pref << 8) | (unsigned)d;
            S.rem = (unsigned)rem;
        }
        __syncthreads();
        unsigned pref28 = S.pref;
        if (tid < 16) S.h2[tid] = 0;
        __syncthreads();
        for (int i = tid; i < cnt; i += 256) {
            unsigned u = S.cand_u[i];
            if ((u >> 4) == pref28) atomicAdd(&S.h2[u & 15u], 1u);
        }
        __syncthreads();
        if (tid == 0) {
            int rem = (int)S.rem; int d = 15;
            for (; d > 0; --d) { if (rem > (int)S.h2[d]) rem -= (int)S.h2[d]; else break; }
            S.pref = (S.pref << 4) | (unsigned)d;  // full 32-bit threshold
            S.rem = (unsigned)rem;
        }
        __syncthreads();

        // d) tie cleanup: keep exactly S.rem threshold-valued elements
        unsigned thr = S.pref, keep = S.rem;
        for (int i = tid; i < cnt; i += 256) {
            if (S.cand_u[i] == thr) {
                unsigned pcl = atomicAdd(&S.claim, 1u);
                if (pcl >= keep)
                    d_g[b * NPATCH + S.cand_i[i]] = __uint_as_float(0xFF800000u); // -inf
            }
        }

        // e) reset this image's histogram for the next invocation
        __syncthreads();
        #pragma unroll
        for (int k = 0; k < 16; k++)
            d_hist[b * NBINS + k * 256 + tid] = 0u;

        // f) RELEASE the threshold (orders the tie writes before it)
        __syncthreads();
        if (tid == 0) {
            __threadfence();
            atomicExch(&d_thr[b], thr);    // thr != 0 for finite scores
        }
        return;
    }

    // ================= apply path =================
    int n   = blockIdx.x - BATCH;
    int b   = n / APB;
    int r   = n - b * APB;
    int h   = r / 14;                                // 0..55 (quarter rows)
    int w4off = (r - h * 14) * 256 + tid;            // 0..3583
    int w   = w4off >> 4;

    // spin until this image's threshold is published (tid0 only, broadcast)
    if (tid == 0) {
        unsigned t;
        while ((t = atomicOr(&d_thr[b], 0u)) == 0u) __nanosleep(64);
        S.pref = t;
    }
    __syncthreads();
    unsigned thr = S.pref;
    // d_g reads below are this block's FIRST accesses post-launch-L1-flush,
    // so they fetch from L2 and see the selector's writes (no fence needed).

    const float* gb = d_g + b * NPATCH;
    int gcol = w >> 1;
    int grow = h >> 1;

    float gv[4];
    #pragma unroll
    for (int j = 0; j < 4; j++) {
        float s = __ldg(&gb[(grow + 28 * j) * WO + gcol]);
        gv[j] = (f2o(s) >= thr) ? s : 0.0f;
    }

    int i0 = b * IMG4 + h * ROW4 + w4off;
    const float4* x4 = (const float4*)x;
    float4*       o4 = (float4*)out;

    float4 rr[4];
    #pragma unroll
    for (int j = 0; j < 4; j++) {
        float gg = gv[j];
        if (gg != 0.0f) {
            float4 v = __ldg(&x4[i0 + j * QTR4]);
            rr[j] = make_float4(v.x * gg, v.y * gg, v.z * gg, v.w * gg);
        } else {
            rr[j] = make_float4(0.f, 0.f, 0.f, 0.f);
        }
    }
    #pragma unroll
    for (int j = 0; j < 4; j++)
        __stcs(&o4[i0 + j * QTR4], rr[j]);

    // arrival: the 784th apply block of image b resets the handshake state
    __syncthreads();
    if (tid == 0) {
        unsigned a = atomicAdd(&d_adone[b], 1u);
        if (a == APB - 1) {
            d_adone[b] = 0u;
            atomicExch(&d_thr[b], 0u);
        }
    }
}

// ---------------------------------------------------------------------------
extern "C" void kernel_launch(void* const* d_in, const int* in_sizes, int n_in,
                              void* d_out, int out_size) {
    const float* x  = (const float*)d_in[0];
    const float* wk = (const float*)d_in[1];
    float* out = (float*)d_out;

    // 1) conv + fused histogram
    dim3 cgrid(392, BATCH);
    conv_gate_k<<<cgrid, 256>>>(x, wk);

    // 2) fused selector (16 blocks) + apply (12544 blocks)
    selapply_k<<<BATCH + APB * BATCH, 256>>>(x, out);
}